// round 12
// baseline (speedup 1.0000x reference)
#include <cuda_runtime.h>
#include <cstdint>

#define BB 64
#define SS 400
#define HH 512
#define EE 300
#define VOCAB 50000
#define KOUT 1024
#define KG   1324
#define KPAD 1536
#define GR   2048

#define OUT_H_OFF (BB * VOCAB)
#define OUT_C_OFF (BB * VOCAB + BB * HH)

// ---------------- scratch ----------------------------------------------------
__device__ float g_attw[BB * SS];
__device__ float g_score[BB * SS];
__device__ float g_gcat[BB * KPAD];     // [b][k]: xe | ctx | hprev | 0-pad (exact fp32)
__device__ float g_outcat[BB * KOUT];   // [b][k]: h_new | ctx  (tf32-rounded bits)
__device__ float g_gates[BB * GR];
__device__ float g_pgen[BB];
__device__ unsigned int g_arrive;       // monotonically growing; epoch = value/128

__device__ __forceinline__ float fast_tanh(float x) {
    float e = __expf(x + x);
    return 1.f - __fdividef(2.f, e + 1.f);
}
__device__ __forceinline__ float fast_sigm(float x) {
    return __fdividef(1.f, 1.f + __expf(-x));
}
__device__ __forceinline__ uint32_t f2tf32(float x) {
    uint32_t r; asm("cvt.rna.tf32.f32 %0, %1;" : "=r"(r) : "f"(x)); return r;
}
__device__ __forceinline__ float tf32r(float x) {
    return __uint_as_float(f2tf32(x));
}
__device__ __forceinline__ void mma_tf32(float* d, const uint32_t* a, const uint32_t* b) {
    asm volatile("mma.sync.aligned.m16n8k8.row.col.f32.tf32.tf32.f32 "
                 "{%0,%1,%2,%3}, {%4,%5,%6,%7}, {%8,%9}, {%0,%1,%2,%3};"
                 : "+f"(d[0]), "+f"(d[1]), "+f"(d[2]), "+f"(d[3])
                 : "r"(a[0]), "r"(a[1]), "r"(a[2]), "r"(a[3]),
                   "r"(b[0]), "r"(b[1]));
}
__device__ __forceinline__ uint32_t smem_u32(const void* p) {
    uint32_t a;
    asm("{ .reg .u64 t; cvta.to.shared.u64 t, %1; cvt.u32.u64 %0, t; }" : "=r"(a) : "l"(p));
    return a;
}
__device__ __forceinline__ void cp_async16(uint32_t dst, const void* src, int src_bytes) {
    asm volatile("cp.async.cg.shared.global [%0], [%1], 16, %2;"
                 :: "r"(dst), "l"(src), "r"(src_bytes) : "memory");
}
#define CP_COMMIT() asm volatile("cp.async.commit_group;" ::: "memory")
#define CP_WAIT(n)  asm volatile("cp.async.wait_group %0;" :: "n"(n) : "memory")

extern __shared__ float dynsmem[];

// ---------------- scores (grid 64 x 4) + one-time staging ----------------------
__global__ void __launch_bounds__(256) k_score(const int* __restrict__ x,
                                               const float* __restrict__ emb,
                                               const float* __restrict__ enc,
                                               const float* __restrict__ h0,
                                               const float* __restrict__ Vw,
                                               const float* __restrict__ Vb,
                                               const float* __restrict__ bih,
                                               const float* __restrict__ bhh) {
    __shared__ float sh_h[HH];
    __shared__ float sh_vw[HH];
    int b = blockIdx.x, q4 = blockIdx.y;
    int t = threadIdx.x;
    int lane = t & 31, w = t >> 5;

    for (int i = t; i < HH; i += 256) {
        float hv = h0[b * HH + i];
        sh_h[i] = hv;
        sh_vw[i] = Vw[i];
        if (q4 == 0) g_gcat[b * KPAD + 812 + i] = hv;
    }
    if (q4 == 0) {
        int row = x[b];
        for (int i = t; i < EE; i += 256)
            g_gcat[b * KPAD + i] = emb[(size_t)row * EE + i];
        for (int i = t; i < GR; i += 256)
            g_gates[b * GR + i] = bih[i] + bhh[i];
    }
    __syncthreads();

    const float* encb = enc + (size_t)b * (SS * HH);
    float vb = Vb[0];
    int s0 = q4 * 100;
    for (int s = s0 + w; s < s0 + 100; s += 8) {
        const float* row = encb + s * HH;
        float p = 0.f;
#pragma unroll
        for (int j = 0; j < 16; j++) {
            int h = j * 32 + lane;
            p += fast_tanh(row[h] + sh_h[h]) * sh_vw[h];
        }
#pragma unroll
        for (int o = 16; o; o >>= 1) p += __shfl_xor_sync(~0u, p, o);
        if (lane == 0) g_score[b * SS + s] = p + vb;
    }
}

// ---------------- softmax + ctx (grid 64 x 2, h-halves) ------------------------
__global__ void __launch_bounds__(256) k_ctx(const float* __restrict__ enc) {
    __shared__ float sh_w[SS];
    __shared__ float sh_red[8];
    int b = blockIdx.x, hh = blockIdx.y;
    int t = threadIdx.x;
    int lane = t & 31, w = t >> 5;

    for (int s = t; s < SS; s += 256) sh_w[s] = g_score[b * SS + s];
    __syncthreads();

    float m = -3.4e38f;
    for (int s = t; s < SS; s += 256) m = fmaxf(m, sh_w[s]);
#pragma unroll
    for (int o = 16; o; o >>= 1) m = fmaxf(m, __shfl_xor_sync(~0u, m, o));
    if (lane == 0) sh_red[w] = m;
    __syncthreads();
    m = sh_red[0];
#pragma unroll
    for (int i = 1; i < 8; i++) m = fmaxf(m, sh_red[i]);
    __syncthreads();

    float ssum = 0.f;
    for (int s = t; s < SS; s += 256) {
        float e = __expf(sh_w[s] - m);
        sh_w[s] = e;
        ssum += e;
    }
#pragma unroll
    for (int o = 16; o; o >>= 1) ssum += __shfl_xor_sync(~0u, ssum, o);
    if (lane == 0) sh_red[w] = ssum;
    __syncthreads();
    ssum = 0.f;
#pragma unroll
    for (int i = 0; i < 8; i++) ssum += sh_red[i];
    float inv = 1.f / ssum;
    __syncthreads();

    for (int s = t; s < SS; s += 256) {
        float wv = sh_w[s] * inv;
        sh_w[s] = wv;
        if (hh == 0) g_attw[b * SS + s] = wv;
    }
    __syncthreads();

    int h = hh * 256 + t;
    const float* encb = enc + (size_t)b * (SS * HH) + h;
    float a = 0.f;
#pragma unroll 4
    for (int s = 0; s < SS; s++) a = fmaf(sh_w[s], encb[s * HH], a);
    g_outcat[b * KOUT + 512 + h] = tf32r(a);
    g_gcat[b * KPAD + 300 + h] = a;
}

// ---------------- gates GEMM + fused LSTM/p_gen tail ---------------------------
// grid (16, 8) = 128 CTAs, all co-resident. Epoch-based arrival tickets:
// every invocation adds exactly 128 to g_arrive, so at entry the counter is a
// multiple of 128. slot = ticket & 127 (always 0..127 -> no OOB under ncu
// standalone replays); wait target = (ticket & ~127) + 128. No reset needed.
#define GP 36
#define G_ASZ (64 * GP)
#define G_BSZ (128 * GP)
#define G_STG (G_ASZ + G_BSZ)
__global__ void __launch_bounds__(256, 2) k_gates(const float* __restrict__ Wih,
                                                  const float* __restrict__ Whh,
                                                  const float* __restrict__ c0,
                                                  const float* __restrict__ genw,
                                                  const float* __restrict__ genb,
                                                  float* __restrict__ out) {
    __shared__ float sred[8];
    __shared__ unsigned int s_tk;
    int t = threadIdx.x;
    int wid = t >> 5, lane = t & 31;
    int gid = lane >> 2, tig = lane & 3;
    int r0 = blockIdx.x * 128;
    int cbase = blockIdx.y * 6;
    int m0 = (wid & 1) * 32;
    int n0 = (wid >> 1) * 32;
    uint32_t smb = smem_u32(dynsmem);

    float acc[2][4][4];
#pragma unroll
    for (int mt = 0; mt < 2; mt++)
#pragma unroll
        for (int nt = 0; nt < 4; nt++)
#pragma unroll
            for (int p = 0; p < 4; p++) acc[mt][nt][p] = 0.f;

#define G_ISSUE(s, c) do {                                                         \
        uint32_t sa = smb + (s) * G_STG * 4;                                       \
        uint32_t sb = sa + G_ASZ * 4;                                              \
        int kbase = (c) * 32;                                                      \
        _Pragma("unroll")                                                          \
        for (int q = 0; q < 2; q++) {                                              \
            int i = q * 256 + t, row = i >> 3, c4 = i & 7;                         \
            cp_async16(sa + (row * GP + c4 * 4) * 4,                               \
                       g_gcat + (size_t)row * KPAD + kbase + c4 * 4, 16);          \
        }                                                                          \
        _Pragma("unroll")                                                          \
        for (int q = 0; q < 4; q++) {                                              \
            int i = q * 256 + t, row = i >> 3, c4 = i & 7;                         \
            int gr = r0 + row, k = kbase + c4 * 4;                                 \
            const float* src; int sz = 16;                                         \
            if (k < 812)       src = Wih + (size_t)gr * 812 + k;                   \
            else if (k < KG)   src = Whh + (size_t)gr * 512 + (k - 812);           \
            else             { src = Whh; sz = 0; }                                \
            cp_async16(sb + (row * GP + c4 * 4) * 4, src, sz);                     \
        }                                                                          \
        CP_COMMIT();                                                               \
    } while (0)

    G_ISSUE(0, cbase);
    for (int j = 0; j < 6; j++) {
        if (j + 1 < 6) G_ISSUE((j + 1) & 1, cbase + j + 1); else CP_COMMIT();
        CP_WAIT(1);
        __syncthreads();
        const float* sA = dynsmem + (j & 1) * G_STG;
        const float* sB = sA + G_ASZ;
#pragma unroll
        for (int ks = 0; ks < 4; ks++) {
            int kb = ks * 8;
            uint32_t a[2][4], b[4][2];
#pragma unroll
            for (int mt = 0; mt < 2; mt++) {
                int r = m0 + mt * 16 + gid;
                a[mt][0] = f2tf32(sA[r * GP + kb + tig]);
                a[mt][1] = f2tf32(sA[(r + 8) * GP + kb + tig]);
                a[mt][2] = f2tf32(sA[r * GP + kb + tig + 4]);
                a[mt][3] = f2tf32(sA[(r + 8) * GP + kb + tig + 4]);
            }
#pragma unroll
            for (int nt = 0; nt < 4; nt++) {
                int rn = n0 + nt * 8 + gid;
                b[nt][0] = f2tf32(sB[rn * GP + kb + tig]);
                b[nt][1] = f2tf32(sB[rn * GP + kb + tig + 4]);
            }
#pragma unroll
            for (int mt = 0; mt < 2; mt++)
#pragma unroll
                for (int nt = 0; nt < 4; nt++)
                    mma_tf32(acc[mt][nt], a[mt], b[nt]);
        }
        __syncthreads();
    }

#pragma unroll
    for (int mt = 0; mt < 2; mt++) {
        int r = m0 + mt * 16 + gid;
#pragma unroll
        for (int nt = 0; nt < 4; nt++) {
            int col = r0 + n0 + nt * 8 + 2 * tig;
            atomicAdd(&g_gates[r * GR + col],       acc[mt][nt][0]);
            atomicAdd(&g_gates[r * GR + col + 1],   acc[mt][nt][1]);
            atomicAdd(&g_gates[(r + 8) * GR + col],     acc[mt][nt][2]);
            atomicAdd(&g_gates[(r + 8) * GR + col + 1], acc[mt][nt][3]);
        }
    }

    // ---- epoch-based arrival ticket + fused LSTM/p_gen tail ----
    __threadfence();
    __syncthreads();                       // all threads' atomics flushed
    if (t == 0) s_tk = atomicAdd(&g_arrive, 1u);
    __syncthreads();
    unsigned int tk = s_tk;
    unsigned int slot = tk & 127u;
    unsigned int target = (tk & ~127u) + 128u;
    if (slot < 64) return;
    int b = (int)(slot - 64);
    if (t == 0) {
        while (atomicAdd(&g_arrive, 0u) < target) __nanosleep(128);
    }
    __syncthreads();
    __threadfence();

    float p = 0.f;
#pragma unroll
    for (int q = 0; q < 2; q++) {
        int h = t + q * 256;      // h covers 0..511
        const float* g = g_gates + b * GR;
        float gi = __ldcg(&g[h]);
        float gf = __ldcg(&g[HH + h]);
        float gg = __ldcg(&g[2 * HH + h]);
        float go = __ldcg(&g[3 * HH + h]);
        float c = fast_sigm(gf) * c0[b * HH + h] + fast_sigm(gi) * fast_tanh(gg);
        float hn = fast_sigm(go) * fast_tanh(c);
        out[OUT_H_OFF + b * HH + h] = hn;
        out[OUT_C_OFF + b * HH + h] = c;
        g_outcat[b * KOUT + h] = tf32r(hn);
        // p_gen partials: gen_in = [ctx(512), h_new(512), xe(300)]
        p = fmaf(genw[h], g_gcat[b * KPAD + 300 + h], p);   // ctx exact
        p = fmaf(genw[512 + h], hn, p);                     // h_new
        if (h < EE)
            p = fmaf(genw[1024 + h], g_gcat[b * KPAD + h], p);  // xe (covers 0..299)
    }
#pragma unroll
    for (int o = 16; o; o >>= 1) p += __shfl_xor_sync(~0u, p, o);
    if (lane == 0) sred[wid] = p;
    __syncthreads();
    if (t == 0) {
        float s = 0.f;
#pragma unroll
        for (int i = 0; i < 8; i++) s += sred[i];
        g_pgen[b] = fast_sigm(s + genb[0]);
    }
}

// ---------------- output GEMM: tf32 mma, CTA 64x256, warp 32x64, 2-stage -------
// (measured-best config: 81.5us, 124 regs, 2 CTA/SM)
#define OP 36
#define O_ASZ (64 * OP)
#define O_BSZ (256 * OP)
#define O_STG (O_ASZ + O_BSZ)
__global__ void __launch_bounds__(256, 2) k_outgemm(const float* __restrict__ outw,
                                                    const float* __restrict__ outb,
                                                    float* __restrict__ out) {
    int t = threadIdx.x;
    int wid = t >> 5, lane = t & 31;
    int gid = lane >> 2, tig = lane & 3;
    int nb = blockIdx.x * 256;
    int m0 = (wid & 1) * 32;
    int n0 = (wid >> 1) * 64;
    uint32_t smb = smem_u32(dynsmem);

    float acc[2][8][4];
#pragma unroll
    for (int mt = 0; mt < 2; mt++)
#pragma unroll
        for (int nt = 0; nt < 8; nt++)
#pragma unroll
            for (int p = 0; p < 4; p++) acc[mt][nt][p] = 0.f;

#define O_ISSUE(s, kc) do {                                                        \
        uint32_t sa = smb + (s) * O_STG * 4;                                       \
        uint32_t sb = sa + O_ASZ * 4;                                              \
        int kbase = (kc) * 32;                                                     \
        _Pragma("unroll")                                                          \
        for (int q = 0; q < 2; q++) {                                              \
            int i = q * 256 + t, row = i >> 3, c4 = i & 7;                         \
            cp_async16(sa + (row * OP + c4 * 4) * 4,                               \
                       g_outcat + (size_t)row * KOUT + kbase + c4 * 4, 16);        \
        }                                                                          \
        _Pragma("unroll")                                                          \
        for (int q = 0; q < 8; q++) {                                              \
            int i = q * 256 + t, row = i >> 3, c4 = i & 7;                         \
            int vr = nb + row;                                                     \
            const float* src = outw;                                               \
            int sz = 0;                                                            \
            if (vr < VOCAB) { src = outw + (size_t)vr * KOUT + kbase + c4 * 4; sz = 16; } \
            cp_async16(sb + (row * OP + c4 * 4) * 4, src, sz);                     \
        }                                                                          \
        CP_COMMIT();                                                               \
    } while (0)

    O_ISSUE(0, 0);
    for (int kc = 0; kc < 32; kc++) {
        if (kc + 1 < 32) O_ISSUE((kc + 1) & 1, kc + 1); else CP_COMMIT();
        CP_WAIT(1);
        __syncthreads();
        const uint32_t* sA = reinterpret_cast<const uint32_t*>(dynsmem + (kc & 1) * O_STG);
        const float*    sB = dynsmem + (kc & 1) * O_STG + O_ASZ;
#pragma unroll
        for (int ks = 0; ks < 4; ks++) {
            int kb = ks * 8;
            uint32_t a[2][4], b[8][2];
#pragma unroll
            for (int mt = 0; mt < 2; mt++) {
                int r = m0 + mt * 16 + gid;
                a[mt][0] = sA[r * OP + kb + tig];
                a[mt][1] = sA[(r + 8) * OP + kb + tig];
                a[mt][2] = sA[r * OP + kb + tig + 4];
                a[mt][3] = sA[(r + 8) * OP + kb + tig + 4];
            }
#pragma unroll
            for (int nt = 0; nt < 8; nt++) {
                int rn = n0 + nt * 8 + gid;
                b[nt][0] = f2tf32(sB[rn * OP + kb + tig]);
                b[nt][1] = f2tf32(sB[rn * OP + kb + tig + 4]);
            }
#pragma unroll
            for (int mt = 0; mt < 2; mt++)
#pragma unroll
                for (int nt = 0; nt < 8; nt++)
                    mma_tf32(acc[mt][nt], a[mt], b[nt]);
        }
        __syncthreads();
    }

#pragma unroll
    for (int mt = 0; mt < 2; mt++) {
        int r = m0 + mt * 16 + gid;
        float pg0 = g_pgen[r], pg1 = g_pgen[r + 8];
#pragma unroll
        for (int nt = 0; nt < 8; nt++) {
            int v0 = nb + n0 + nt * 8 + 2 * tig;
            if (v0 < VOCAB) {
                float2 ob = *reinterpret_cast<const float2*>(outb + v0);
                float2 o0, o1;
                o0.x = pg0 * (acc[mt][nt][0] + ob.x);
                o0.y = pg0 * (acc[mt][nt][1] + ob.y);
                o1.x = pg1 * (acc[mt][nt][2] + ob.x);
                o1.y = pg1 * (acc[mt][nt][3] + ob.y);
                *reinterpret_cast<float2*>(out + (size_t)r * VOCAB + v0) = o0;
                *reinterpret_cast<float2*>(out + (size_t)(r + 8) * VOCAB + v0) = o1;
            }
        }
    }
}

// ---------------- pointer scatter ----------------------------------------------
__global__ void k_scatter(const int* __restrict__ text, float* __restrict__ out) {
    __shared__ int sv[SS];
    __shared__ float sw[SS];
    int b = blockIdx.x, t = threadIdx.x;
    for (int s = t; s < SS; s += 256) {
        sv[s] = text[b * SS + s];
        sw[s] = g_attw[b * SS + s];
    }
    __syncthreads();
    float pptr = 1.f - g_pgen[b];
    for (int s = t; s < SS; s += 256) {
        int v = sv[s];
        bool last = true;
        for (int s2 = s + 1; s2 < SS; s2++)
            if (sv[s2] == v) { last = false; break; }
        if (last) out[(size_t)b * VOCAB + v] += pptr * sw[s];
    }
}

// ---------------- launch --------------------------------------------------------
extern "C" void kernel_launch(void* const* d_in, const int* in_sizes, int n_in,
                              void* d_out, int out_size) {
    int sh = (n_in >= 17 && in_sizes[5] == 1) ? 1 : 0;
    const int*   x    = (const int*)  d_in[0];
    const float* enc  = (const float*)d_in[1];
    const float* h0   = (const float*)d_in[2];
    const float* c0   = (const float*)d_in[3];
    const int*   text = (const int*)  d_in[4];
    const float* emb  = (const float*)d_in[5 + sh];
    const float* Vw   = (const float*)d_in[6 + sh];
    const float* Vb   = (const float*)d_in[7 + sh];
    const float* genw = (const float*)d_in[8 + sh];
    const float* genb = (const float*)d_in[9 + sh];
    const float* outw = (const float*)d_in[10 + sh];
    const float* outb = (const float*)d_in[11 + sh];
    const float* Wih  = (const float*)d_in[12 + sh];
    const float* Whh  = (const float*)d_in[13 + sh];
    const float* bih  = (const float*)d_in[14 + sh];
    const float* bhh  = (const float*)d_in[15 + sh];
    float* out = (float*)d_out;

    cudaFuncSetAttribute(k_outgemm, cudaFuncAttributeMaxDynamicSharedMemorySize,
                         2 * O_STG * 4);
    cudaFuncSetAttribute(k_gates, cudaFuncAttributeMaxDynamicSharedMemorySize,
                         2 * G_STG * 4);

    dim3 gsc(64, 4);
    k_score<<<gsc, 256>>>(x, emb, enc, h0, Vw, Vb, bih, bhh);
    dim3 gcx(64, 2);
    k_ctx<<<gcx, 256>>>(enc);
    dim3 gg(16, 8);
    k_gates<<<gg, 256, 2 * G_STG * 4>>>(Wih, Whh, c0, genw, genb, out);
    k_outgemm<<<196, 256, 2 * O_STG * 4>>>(outw, outb, out);   // ncu slot 4
    k_scatter<<<64, 256>>>(text, out);
}

// round 13
// speedup vs baseline: 1.2671x; 1.2671x over previous
#include <cuda_runtime.h>
#include <cstdint>

#define BB 64
#define SS 400
#define HH 512
#define EE 300
#define VOCAB 50000
#define KOUT 1024
#define KG   1324
#define KPAD 1536
#define GR   2048

#define OUT_H_OFF (BB * VOCAB)
#define OUT_C_OFF (BB * VOCAB + BB * HH)

// ---------------- scratch ----------------------------------------------------
__device__ float g_attw[BB * SS];
__device__ float g_score[BB * SS];
__device__ float g_gcat[BB * KPAD];     // [b][k]: xe | ctx(accum) | hprev | 0-pad
__device__ float g_outcat[BB * KOUT];   // [b][k]: h_new | ctx  (tf32-rounded bits)
__device__ float g_gates[BB * GR];
__device__ float g_pgen[BB];
__device__ unsigned int g_arrive;       // monotonically growing; epoch = value/128

__device__ __forceinline__ float fast_tanh(float x) {
    float e = __expf(x + x);
    return 1.f - __fdividef(2.f, e + 1.f);
}
__device__ __forceinline__ float fast_sigm(float x) {
    return __fdividef(1.f, 1.f + __expf(-x));
}
__device__ __forceinline__ uint32_t f2tf32(float x) {
    uint32_t r; asm("cvt.rna.tf32.f32 %0, %1;" : "=r"(r) : "f"(x)); return r;
}
__device__ __forceinline__ float tf32r(float x) {
    return __uint_as_float(f2tf32(x));
}
__device__ __forceinline__ void mma_tf32(float* d, const uint32_t* a, const uint32_t* b) {
    asm volatile("mma.sync.aligned.m16n8k8.row.col.f32.tf32.tf32.f32 "
                 "{%0,%1,%2,%3}, {%4,%5,%6,%7}, {%8,%9}, {%0,%1,%2,%3};"
                 : "+f"(d[0]), "+f"(d[1]), "+f"(d[2]), "+f"(d[3])
                 : "r"(a[0]), "r"(a[1]), "r"(a[2]), "r"(a[3]),
                   "r"(b[0]), "r"(b[1]));
}
__device__ __forceinline__ uint32_t smem_u32(const void* p) {
    uint32_t a;
    asm("{ .reg .u64 t; cvta.to.shared.u64 t, %1; cvt.u32.u64 %0, t; }" : "=r"(a) : "l"(p));
    return a;
}
__device__ __forceinline__ void cp_async16(uint32_t dst, const void* src, int src_bytes) {
    asm volatile("cp.async.cg.shared.global [%0], [%1], 16, %2;"
                 :: "r"(dst), "l"(src), "r"(src_bytes) : "memory");
}
#define CP_COMMIT() asm volatile("cp.async.commit_group;" ::: "memory")
#define CP_WAIT(n)  asm volatile("cp.async.wait_group %0;" :: "n"(n) : "memory")

extern __shared__ float dynsmem[];

// ---------------- scores (grid 64 x 8) + one-time staging ----------------------
__global__ void __launch_bounds__(256) k_score(const int* __restrict__ x,
                                               const float* __restrict__ emb,
                                               const float* __restrict__ enc,
                                               const float* __restrict__ h0,
                                               const float* __restrict__ Vw,
                                               const float* __restrict__ Vb,
                                               const float* __restrict__ bih,
                                               const float* __restrict__ bhh) {
    __shared__ float sh_h[HH];
    __shared__ float sh_vw[HH];
    int b = blockIdx.x, q8 = blockIdx.y;
    int t = threadIdx.x;
    int lane = t & 31, w = t >> 5;

    for (int i = t; i < HH; i += 256) {
        float hv = h0[b * HH + i];
        sh_h[i] = hv;
        sh_vw[i] = Vw[i];
        if (q8 == 0) {
            g_gcat[b * KPAD + 812 + i] = hv;
            g_gcat[b * KPAD + 300 + i] = 0.f;   // zero ctx accumulator
        }
    }
    if (q8 == 0) {
        int row = x[b];
        for (int i = t; i < EE; i += 256)
            g_gcat[b * KPAD + i] = emb[(size_t)row * EE + i];
        for (int i = t; i < GR; i += 256)
            g_gates[b * GR + i] = bih[i] + bhh[i];
    }
    __syncthreads();

    const float* encb = enc + (size_t)b * (SS * HH);
    float vb = Vb[0];
    int s0 = q8 * 50;
    for (int s = s0 + w; s < s0 + 50; s += 8) {
        const float* row = encb + s * HH;
        float p = 0.f;
#pragma unroll
        for (int j = 0; j < 16; j++) {
            int h = j * 32 + lane;
            p += fast_tanh(row[h] + sh_h[h]) * sh_vw[h];
        }
#pragma unroll
        for (int o = 16; o; o >>= 1) p += __shfl_xor_sync(~0u, p, o);
        if (lane == 0) g_score[b * SS + s] = p + vb;
    }
}

// ---------------- softmax (grid 64) — weights computed ONCE --------------------
__global__ void __launch_bounds__(256) k_softmax() {
    __shared__ float sh_w[SS];
    __shared__ float sh_red[8];
    int b = blockIdx.x;
    int t = threadIdx.x;
    int lane = t & 31, w = t >> 5;

    for (int s = t; s < SS; s += 256) sh_w[s] = g_score[b * SS + s];
    __syncthreads();

    float m = -3.4e38f;
    for (int s = t; s < SS; s += 256) m = fmaxf(m, sh_w[s]);
#pragma unroll
    for (int o = 16; o; o >>= 1) m = fmaxf(m, __shfl_xor_sync(~0u, m, o));
    if (lane == 0) sh_red[w] = m;
    __syncthreads();
    m = sh_red[0];
#pragma unroll
    for (int i = 1; i < 8; i++) m = fmaxf(m, sh_red[i]);
    __syncthreads();

    float ssum = 0.f;
    for (int s = t; s < SS; s += 256) {
        float e = __expf(sh_w[s] - m);
        sh_w[s] = e;
        ssum += e;
    }
#pragma unroll
    for (int o = 16; o; o >>= 1) ssum += __shfl_xor_sync(~0u, ssum, o);
    if (lane == 0) sh_red[w] = ssum;
    __syncthreads();
    ssum = 0.f;
#pragma unroll
    for (int i = 0; i < 8; i++) ssum += sh_red[i];
    float inv = 1.f / ssum;

    for (int s = t; s < SS; s += 256)
        g_attw[b * SS + s] = sh_w[s] * inv;
}

// ---------------- ctx partial sums (grid 64 x 8, s-blocks of 50) ---------------
__global__ void __launch_bounds__(256) k_ctx2(const float* __restrict__ enc) {
    __shared__ float sh_w[50];
    int b = blockIdx.x, sb = blockIdx.y;
    int t = threadIdx.x;
    int s0 = sb * 50;

    if (t < 50) sh_w[t] = g_attw[b * SS + s0 + t];
    __syncthreads();

    const float* encb = enc + (size_t)b * (SS * HH) + (size_t)s0 * HH;
    float a0 = 0.f, a1 = 0.f;
#pragma unroll 5
    for (int s = 0; s < 50; s++) {
        float wv = sh_w[s];
        a0 = fmaf(wv, encb[s * HH + t], a0);
        a1 = fmaf(wv, encb[s * HH + t + 256], a1);
    }
    atomicAdd(&g_gcat[b * KPAD + 300 + t], a0);
    atomicAdd(&g_gcat[b * KPAD + 300 + t + 256], a1);
}

// ---------------- gates GEMM + fused LSTM/p_gen/ctx-staging tail ---------------
// grid (16, 8) = 128 CTAs, all co-resident. Epoch-based arrival tickets.
#define GP 36
#define G_ASZ (64 * GP)
#define G_BSZ (128 * GP)
#define G_STG (G_ASZ + G_BSZ)
__global__ void __launch_bounds__(256, 2) k_gates(const float* __restrict__ Wih,
                                                  const float* __restrict__ Whh,
                                                  const float* __restrict__ c0,
                                                  const float* __restrict__ genw,
                                                  const float* __restrict__ genb,
                                                  float* __restrict__ out) {
    __shared__ float sred[8];
    __shared__ unsigned int s_tk;
    int t = threadIdx.x;
    int wid = t >> 5, lane = t & 31;
    int gid = lane >> 2, tig = lane & 3;
    int r0 = blockIdx.x * 128;
    int cbase = blockIdx.y * 6;
    int m0 = (wid & 1) * 32;
    int n0 = (wid >> 1) * 32;
    uint32_t smb = smem_u32(dynsmem);

    float acc[2][4][4];
#pragma unroll
    for (int mt = 0; mt < 2; mt++)
#pragma unroll
        for (int nt = 0; nt < 4; nt++)
#pragma unroll
            for (int p = 0; p < 4; p++) acc[mt][nt][p] = 0.f;

#define G_ISSUE(s, c) do {                                                         \
        uint32_t sa = smb + (s) * G_STG * 4;                                       \
        uint32_t sb = sa + G_ASZ * 4;                                              \
        int kbase = (c) * 32;                                                      \
        _Pragma("unroll")                                                          \
        for (int q = 0; q < 2; q++) {                                              \
            int i = q * 256 + t, row = i >> 3, c4 = i & 7;                         \
            cp_async16(sa + (row * GP + c4 * 4) * 4,                               \
                       g_gcat + (size_t)row * KPAD + kbase + c4 * 4, 16);          \
        }                                                                          \
        _Pragma("unroll")                                                          \
        for (int q = 0; q < 4; q++) {                                              \
            int i = q * 256 + t, row = i >> 3, c4 = i & 7;                         \
            int gr = r0 + row, k = kbase + c4 * 4;                                 \
            const float* src; int sz = 16;                                         \
            if (k < 812)       src = Wih + (size_t)gr * 812 + k;                   \
            else if (k < KG)   src = Whh + (size_t)gr * 512 + (k - 812);           \
            else             { src = Whh; sz = 0; }                                \
            cp_async16(sb + (row * GP + c4 * 4) * 4, src, sz);                     \
        }                                                                          \
        CP_COMMIT();                                                               \
    } while (0)

    G_ISSUE(0, cbase);
    for (int j = 0; j < 6; j++) {
        if (j + 1 < 6) G_ISSUE((j + 1) & 1, cbase + j + 1); else CP_COMMIT();
        CP_WAIT(1);
        __syncthreads();
        const float* sA = dynsmem + (j & 1) * G_STG;
        const float* sB = sA + G_ASZ;
#pragma unroll
        for (int ks = 0; ks < 4; ks++) {
            int kb = ks * 8;
            uint32_t a[2][4], b[4][2];
#pragma unroll
            for (int mt = 0; mt < 2; mt++) {
                int r = m0 + mt * 16 + gid;
                a[mt][0] = f2tf32(sA[r * GP + kb + tig]);
                a[mt][1] = f2tf32(sA[(r + 8) * GP + kb + tig]);
                a[mt][2] = f2tf32(sA[r * GP + kb + tig + 4]);
                a[mt][3] = f2tf32(sA[(r + 8) * GP + kb + tig + 4]);
            }
#pragma unroll
            for (int nt = 0; nt < 4; nt++) {
                int rn = n0 + nt * 8 + gid;
                b[nt][0] = f2tf32(sB[rn * GP + kb + tig]);
                b[nt][1] = f2tf32(sB[rn * GP + kb + tig + 4]);
            }
#pragma unroll
            for (int mt = 0; mt < 2; mt++)
#pragma unroll
                for (int nt = 0; nt < 4; nt++)
                    mma_tf32(acc[mt][nt], a[mt], b[nt]);
        }
        __syncthreads();
    }

#pragma unroll
    for (int mt = 0; mt < 2; mt++) {
        int r = m0 + mt * 16 + gid;
#pragma unroll
        for (int nt = 0; nt < 4; nt++) {
            int col = r0 + n0 + nt * 8 + 2 * tig;
            atomicAdd(&g_gates[r * GR + col],       acc[mt][nt][0]);
            atomicAdd(&g_gates[r * GR + col + 1],   acc[mt][nt][1]);
            atomicAdd(&g_gates[(r + 8) * GR + col],     acc[mt][nt][2]);
            atomicAdd(&g_gates[(r + 8) * GR + col + 1], acc[mt][nt][3]);
        }
    }

    // ---- epoch-based arrival ticket + fused LSTM/p_gen/ctx-staging tail ----
    __threadfence();
    __syncthreads();
    if (t == 0) s_tk = atomicAdd(&g_arrive, 1u);
    __syncthreads();
    unsigned int tk = s_tk;
    unsigned int slot = tk & 127u;
    unsigned int target = (tk & ~127u) + 128u;
    if (slot < 64) return;
    int b = (int)(slot - 64);
    if (t == 0) {
        while (atomicAdd(&g_arrive, 0u) < target) __nanosleep(128);
    }
    __syncthreads();
    __threadfence();

    float p = 0.f;
#pragma unroll
    for (int q = 0; q < 2; q++) {
        int h = t + q * 256;      // h covers 0..511
        const float* g = g_gates + b * GR;
        float gi = __ldcg(&g[h]);
        float gf = __ldcg(&g[HH + h]);
        float gg = __ldcg(&g[2 * HH + h]);
        float go = __ldcg(&g[3 * HH + h]);
        float c = fast_sigm(gf) * c0[b * HH + h] + fast_sigm(gi) * fast_tanh(gg);
        float hn = fast_sigm(go) * fast_tanh(c);
        out[OUT_H_OFF + b * HH + h] = hn;
        out[OUT_C_OFF + b * HH + h] = c;
        g_outcat[b * KOUT + h] = tf32r(hn);
        // ctx: accumulated exact value -> stage tf32-rounded copy for outgemm A
        float ctxv = __ldcg(&g_gcat[b * KPAD + 300 + h]);
        g_outcat[b * KOUT + 512 + h] = tf32r(ctxv);
        // p_gen partials: gen_in = [ctx(512), h_new(512), xe(300)]
        p = fmaf(genw[h], ctxv, p);
        p = fmaf(genw[512 + h], hn, p);
        if (h < EE)
            p = fmaf(genw[1024 + h], g_gcat[b * KPAD + h], p);
    }
#pragma unroll
    for (int o = 16; o; o >>= 1) p += __shfl_xor_sync(~0u, p, o);
    if (lane == 0) sred[wid] = p;
    __syncthreads();
    if (t == 0) {
        float s = 0.f;
#pragma unroll
        for (int i = 0; i < 8; i++) s += sred[i];
        g_pgen[b] = fast_sigm(s + genb[0]);
    }
}

// ---------------- output GEMM: tf32 mma, CTA 64x256, warp 32x64, 2-stage -------
// (measured-best config: 81.0us, 124 regs, 2 CTA/SM)
#define OP 36
#define O_ASZ (64 * OP)
#define O_BSZ (256 * OP)
#define O_STG (O_ASZ + O_BSZ)
__global__ void __launch_bounds__(256, 2) k_outgemm(const float* __restrict__ outw,
                                                    const float* __restrict__ outb,
                                                    float* __restrict__ out) {
    int t = threadIdx.x;
    int wid = t >> 5, lane = t & 31;
    int gid = lane >> 2, tig = lane & 3;
    int nb = blockIdx.x * 256;
    int m0 = (wid & 1) * 32;
    int n0 = (wid >> 1) * 64;
    uint32_t smb = smem_u32(dynsmem);

    float acc[2][8][4];
#pragma unroll
    for (int mt = 0; mt < 2; mt++)
#pragma unroll
        for (int nt = 0; nt < 8; nt++)
#pragma unroll
            for (int p = 0; p < 4; p++) acc[mt][nt][p] = 0.f;

#define O_ISSUE(s, kc) do {                                                        \
        uint32_t sa = smb + (s) * O_STG * 4;                                       \
        uint32_t sb = sa + O_ASZ * 4;                                              \
        int kbase = (kc) * 32;                                                     \
        _Pragma("unroll")                                                          \
        for (int q = 0; q < 2; q++) {                                              \
            int i = q * 256 + t, row = i >> 3, c4 = i & 7;                         \
            cp_async16(sa + (row * OP + c4 * 4) * 4,                               \
                       g_outcat + (size_t)row * KOUT + kbase + c4 * 4, 16);        \
        }                                                                          \
        _Pragma("unroll")                                                          \
        for (int q = 0; q < 8; q++) {                                              \
            int i = q * 256 + t, row = i >> 3, c4 = i & 7;                         \
            int vr = nb + row;                                                     \
            const float* src = outw;                                               \
            int sz = 0;                                                            \
            if (vr < VOCAB) { src = outw + (size_t)vr * KOUT + kbase + c4 * 4; sz = 16; } \
            cp_async16(sb + (row * OP + c4 * 4) * 4, src, sz);                     \
        }                                                                          \
        CP_COMMIT();                                                               \
    } while (0)

    O_ISSUE(0, 0);
    for (int kc = 0; kc < 32; kc++) {
        if (kc + 1 < 32) O_ISSUE((kc + 1) & 1, kc + 1); else CP_COMMIT();
        CP_WAIT(1);
        __syncthreads();
        const uint32_t* sA = reinterpret_cast<const uint32_t*>(dynsmem + (kc & 1) * O_STG);
        const float*    sB = dynsmem + (kc & 1) * O_STG + O_ASZ;
#pragma unroll
        for (int ks = 0; ks < 4; ks++) {
            int kb = ks * 8;
            uint32_t a[2][4], b[8][2];
#pragma unroll
            for (int mt = 0; mt < 2; mt++) {
                int r = m0 + mt * 16 + gid;
                a[mt][0] = sA[r * OP + kb + tig];
                a[mt][1] = sA[(r + 8) * OP + kb + tig];
                a[mt][2] = sA[r * OP + kb + tig + 4];
                a[mt][3] = sA[(r + 8) * OP + kb + tig + 4];
            }
#pragma unroll
            for (int nt = 0; nt < 8; nt++) {
                int rn = n0 + nt * 8 + gid;
                b[nt][0] = f2tf32(sB[rn * OP + kb + tig]);
                b[nt][1] = f2tf32(sB[rn * OP + kb + tig + 4]);
            }
#pragma unroll
            for (int mt = 0; mt < 2; mt++)
#pragma unroll
                for (int nt = 0; nt < 8; nt++)
                    mma_tf32(acc[mt][nt], a[mt], b[nt]);
        }
        __syncthreads();
    }

#pragma unroll
    for (int mt = 0; mt < 2; mt++) {
        int r = m0 + mt * 16 + gid;
        float pg0 = g_pgen[r], pg1 = g_pgen[r + 8];
#pragma unroll
        for (int nt = 0; nt < 8; nt++) {
            int v0 = nb + n0 + nt * 8 + 2 * tig;
            if (v0 < VOCAB) {
                float2 ob = *reinterpret_cast<const float2*>(outb + v0);
                float2 o0, o1;
                o0.x = pg0 * (acc[mt][nt][0] + ob.x);
                o0.y = pg0 * (acc[mt][nt][1] + ob.y);
                o1.x = pg1 * (acc[mt][nt][2] + ob.x);
                o1.y = pg1 * (acc[mt][nt][3] + ob.y);
                *reinterpret_cast<float2*>(out + (size_t)r * VOCAB + v0) = o0;
                *reinterpret_cast<float2*>(out + (size_t)(r + 8) * VOCAB + v0) = o1;
            }
        }
    }
}

// ---------------- pointer scatter ----------------------------------------------
__global__ void k_scatter(const int* __restrict__ text, float* __restrict__ out) {
    __shared__ int sv[SS];
    __shared__ float sw[SS];
    int b = blockIdx.x, t = threadIdx.x;
    for (int s = t; s < SS; s += 256) {
        sv[s] = text[b * SS + s];
        sw[s] = g_attw[b * SS + s];
    }
    __syncthreads();
    float pptr = 1.f - g_pgen[b];
    for (int s = t; s < SS; s += 256) {
        int v = sv[s];
        bool last = true;
        for (int s2 = s + 1; s2 < SS; s2++)
            if (sv[s2] == v) { last = false; break; }
        if (last) out[(size_t)b * VOCAB + v] += pptr * sw[s];
    }
}

// ---------------- launch --------------------------------------------------------
extern "C" void kernel_launch(void* const* d_in, const int* in_sizes, int n_in,
                              void* d_out, int out_size) {
    int sh = (n_in >= 17 && in_sizes[5] == 1) ? 1 : 0;
    const int*   x    = (const int*)  d_in[0];
    const float* enc  = (const float*)d_in[1];
    const float* h0   = (const float*)d_in[2];
    const float* c0   = (const float*)d_in[3];
    const int*   text = (const int*)  d_in[4];
    const float* emb  = (const float*)d_in[5 + sh];
    const float* Vw   = (const float*)d_in[6 + sh];
    const float* Vb   = (const float*)d_in[7 + sh];
    const float* genw = (const float*)d_in[8 + sh];
    const float* genb = (const float*)d_in[9 + sh];
    const float* outw = (const float*)d_in[10 + sh];
    const float* outb = (const float*)d_in[11 + sh];
    const float* Wih  = (const float*)d_in[12 + sh];
    const float* Whh  = (const float*)d_in[13 + sh];
    const float* bih  = (const float*)d_in[14 + sh];
    const float* bhh  = (const float*)d_in[15 + sh];
    float* out = (float*)d_out;

    cudaFuncSetAttribute(k_outgemm, cudaFuncAttributeMaxDynamicSharedMemorySize,
                         2 * O_STG * 4);
    cudaFuncSetAttribute(k_gates, cudaFuncAttributeMaxDynamicSharedMemorySize,
                         2 * G_STG * 4);

    dim3 gsc(64, 8);
    k_score<<<gsc, 256>>>(x, emb, enc, h0, Vw, Vb, bih, bhh);
    k_softmax<<<64, 256>>>();
    dim3 gcx(64, 8);
    k_ctx2<<<gcx, 256>>>(enc);
    dim3 gg(16, 8);
    k_gates<<<gg, 256, 2 * G_STG * 4>>>(Wih, Whh, c0, genw, genb, out);  // ncu slot 4
    k_outgemm<<<196, 256, 2 * O_STG * 4>>>(outw, outb, out);
    k_scatter<<<64, 256>>>(text, out);
}